// round 4
// baseline (speedup 1.0000x reference)
#include <cuda_runtime.h>
#include <cuda_bf16.h>
#include <cstdint>

// ===================== Problem constants =====================

#define BATCH 4096
#define NTOT  8192
#define DIM   128
#define NSTRIPES 64
#define NTILES 2080                       // 64*65/2 upper triangle incl diagonal
#define GRID_K2 148

#define ROW_BYTES 272                     // 256B row + 16B pad (conflict-free ldmatrix)
#define TILE_BYTES (128 * ROW_BYTES)      // 34816
#define SM_CSUM_OFF (4 * TILE_BYTES)      // [A0][B0][A1][B1][csum2[4][128]]
#define SMEM_BYTES (SM_CSUM_OFF + 4 * 128 * 4)

#define EXP_DIAG 7.3890560989306495f      // e^2 self-similarity exp

// ===================== asm helpers (sm_100-safe) =====================

__device__ __forceinline__ uint32_t smem_u32(const void* smem_ptr) {
    uint32_t addr;
    asm("{ .reg .u64 tmp; cvta.to.shared.u64 tmp, %1; cvt.u32.u64 %0, tmp; }"
        : "=r"(addr) : "l"(smem_ptr));
    return addr;
}

#define LDSM_X4(r, addr) \
    asm volatile("ldmatrix.sync.aligned.m8n8.x4.shared.b16 {%0,%1,%2,%3}, [%4];" \
        : "=r"((r)[0]), "=r"((r)[1]), "=r"((r)[2]), "=r"((r)[3]) : "r"(addr))

#define MMA_BF16(d, a, b0, b1) \
    asm volatile("mma.sync.aligned.m16n8k16.row.col.f32.bf16.bf16.f32 " \
        "{%0,%1,%2,%3}, {%4,%5,%6,%7}, {%8,%9}, {%0,%1,%2,%3};" \
        : "+f"((d)[0]), "+f"((d)[1]), "+f"((d)[2]), "+f"((d)[3]) \
        : "r"((a)[0]), "r"((a)[1]), "r"((a)[2]), "r"((a)[3]), "r"(b0), "r"(b1))

#define CP_ASYNC_16(dst_smem, src_gmem) \
    asm volatile("cp.async.cg.shared.global [%0], [%1], 16;" \
        :: "r"(dst_smem), "l"(src_gmem) : "memory")

#define CP_ASYNC_COMMIT() asm volatile("cp.async.commit_group;" ::: "memory")
#define CP_ASYNC_WAIT_1() asm volatile("cp.async.wait_group 1;" ::: "memory")
#define CP_ASYNC_WAIT_0() asm volatile("cp.async.wait_group 0;" ::: "memory")

// ---- packed f32x2 ----

typedef unsigned long long u64;

__device__ __forceinline__ u64 pk2(float lo, float hi) {
    u64 r;
    asm("mov.b64 %0, {%1, %2};" : "=l"(r) : "f"(lo), "f"(hi));
    return r;
}
__device__ __forceinline__ void upk2(float& lo, float& hi, u64 v) {
    asm("mov.b64 {%0, %1}, %2;" : "=f"(lo), "=f"(hi) : "l"(v));
}
__device__ __forceinline__ u64 fma2(u64 a, u64 b, u64 c) {
    u64 d;
    asm("fma.rn.f32x2 %0, %1, %2, %3;" : "=l"(d) : "l"(a), "l"(b), "l"(c));
    return d;
}
__device__ __forceinline__ constexpr u64 dup2c(float f) {
    union { float f32; unsigned int u32; } u = { f };
    return ((u64)u.u32 << 32) | u.u32;
}

// ===================== Device scratch =====================

__device__ __nv_bfloat16 g_zn[NTOT * DIM];
__device__ float g_pos[BATCH];
__device__ float g_rowsum[NTOT];

// ===================== K1: normalize + positives =====================

__global__ void __launch_bounds__(256) k1_normalize(const float* __restrict__ zi,
                                                    const float* __restrict__ zj) {
    const int tid = threadIdx.x;
    const int lane = tid & 31;
    const int r = blockIdx.x * 8 + (tid >> 5);

    const float4 va = reinterpret_cast<const float4*>(zi + r * DIM)[lane];
    const float4 vb = reinterpret_cast<const float4*>(zj + r * DIM)[lane];
    float sa  = va.x*va.x + va.y*va.y + va.z*va.z + va.w*va.w;
    float sb  = vb.x*vb.x + vb.y*vb.y + vb.z*vb.z + vb.w*vb.w;
    float sab = va.x*vb.x + va.y*vb.y + va.z*vb.z + va.w*vb.w;
    #pragma unroll
    for (int o = 16; o; o >>= 1) {
        sa  += __shfl_xor_sync(0xffffffffu, sa,  o);
        sb  += __shfl_xor_sync(0xffffffffu, sb,  o);
        sab += __shfl_xor_sync(0xffffffffu, sab, o);
    }
    const float ri = rsqrtf(fmaxf(sa, 1e-16f));
    const float rj = rsqrtf(fmaxf(sb, 1e-16f));

    __nv_bfloat162 a01 = __floats2bfloat162_rn(va.x * ri, va.y * ri);
    __nv_bfloat162 a23 = __floats2bfloat162_rn(va.z * ri, va.w * ri);
    __nv_bfloat162 b01 = __floats2bfloat162_rn(vb.x * rj, vb.y * rj);
    __nv_bfloat162 b23 = __floats2bfloat162_rn(vb.z * rj, vb.w * rj);
    reinterpret_cast<uint2*>(g_zn + r * DIM)[lane] =
        make_uint2(*reinterpret_cast<uint32_t*>(&a01), *reinterpret_cast<uint32_t*>(&a23));
    reinterpret_cast<uint2*>(g_zn + (r + BATCH) * DIM)[lane] =
        make_uint2(*reinterpret_cast<uint32_t*>(&b01), *reinterpret_cast<uint32_t*>(&b23));

    if (lane == 0) g_pos[r] = sab * ri * rj * 2.0f;
    if (blockIdx.x < 32) g_rowsum[blockIdx.x * 256 + tid] = 0.0f;
}

// ===================== K2: symmetric GEMM + pipelined exp epilogue =====================

__device__ __forceinline__ void decode_tile(int t, int& I, int& J) {
    int i = (int)(64.5f - sqrtf(64.5f * 64.5f - 2.0f * (float)t));
    while (i * (129 - i) / 2 > t) i--;
    while ((i + 1) * (128 - i) / 2 <= t) i++;
    I = i;
    J = i + (t - i * (129 - i) / 2);
}

__global__ void __launch_bounds__(256, 1) k2_simsum() {
    extern __shared__ __align__(16) char dynsm[];
    float (*csum2)[128] = reinterpret_cast<float(*)[128]>(dynsm + SM_CSUM_OFF);

    const int tid = threadIdx.x;
    const int wid = tid >> 5;
    const int lane = tid & 31;
    const int wm = wid & 3;
    const int wn = wid >> 2;

    auto issue = [&](int slot, int I, int J) {
        char* bufA = dynsm + slot * (2 * TILE_BYTES);
        #pragma unroll
        for (int i = 0; i < 8; i++) {
            const int idx = tid + i * 256, row = idx >> 4, c = idx & 15;
            CP_ASYNC_16(smem_u32(bufA + row * ROW_BYTES + c * 16),
                        reinterpret_cast<const uint4*>(g_zn + (I * 128 + row) * DIM) + c);
        }
        if (J != I) {
            char* bufB = bufA + TILE_BYTES;
            #pragma unroll
            for (int i = 0; i < 8; i++) {
                const int idx = tid + i * 256, row = idx >> 4, c = idx & 15;
                CP_ASYNC_16(smem_u32(bufB + row * ROW_BYTES + c * 16),
                            reinterpret_cast<const uint4*>(g_zn + (J * 128 + row) * DIM) + c);
            }
        }
        CP_ASYNC_COMMIT();
    };

    const uint32_t aLane =
        (uint32_t)((wm * 32 + ((lane >> 3) & 1) * 8 + (lane & 7)) * ROW_BYTES)
        + (uint32_t)((lane >> 4) * 16);
    const uint32_t bLane =
        (uint32_t)(((wn * 64) + (lane >> 4) * 8 + (lane & 7)) * ROW_BYTES)
        + (uint32_t)(((lane >> 3) & 1) * 16);

    const u64 C7 = dup2c(1.0f / 5040.0f), C6 = dup2c(1.0f / 720.0f),
              C5 = dup2c(1.0f / 120.0f),  C4 = dup2c(1.0f / 24.0f),
              C3 = dup2c(1.0f / 6.0f),    C2 = dup2c(0.5f), C1 = dup2c(1.0f);

    // pipeline state
    u64 saved[32];                 // packed sim values of the PREVIOUS tile
    u64 prow[4], pcol[8];          // running partials for the previous tile
    #pragma unroll
    for (int k = 0; k < 4; k++) prow[k] = 0ull;
    #pragma unroll
    for (int k = 0; k < 8; k++) pcol[k] = 0ull;

    int t = blockIdx.x;
    int I, J, In, Jn;
    int Ip = 0, Jp = 0;            // previous tile coords
    bool havePrev = false;
    decode_tile(t, I, J);
    issue(0, I, J);
    int slot = 0;

    // one poly chunk: 4 packed pairs of 'saved' -> fold into prow/pcol
    auto epi_chunk = [&](int c) {
        #pragma unroll
        for (int q = 0; q < 4; q++) {
            const int idx = c * 4 + q;          // idx = mb*16 + jj*2 + vp
            const int mb = idx >> 4, jj = (idx >> 1) & 7, vp = idx & 1;
            u64 x = saved[idx];
            u64 p = fma2(C7, x, C6);
            p = fma2(p, x, C5);
            p = fma2(p, x, C4);
            p = fma2(p, x, C3);
            p = fma2(p, x, C2);
            p = fma2(p, x, C1);
            p = fma2(p, x, C1);                 // ~exp(x)
            prow[mb * 2 + vp] = fma2(p, p, prow[mb * 2 + vp]);   // += exp(2x)
            pcol[jj]          = fma2(p, p, pcol[jj]);
        }
    };

    // flush previous tile's row/col sums (uses prow/pcol, Ip/Jp), then reset
    auto flush_prev = [&]() {
        #pragma unroll
        for (int k = 0; k < 4; k++) {
            prow[k] = fma2(C1, __shfl_xor_sync(0xffffffffu, prow[k], 1), prow[k]);
            prow[k] = fma2(C1, __shfl_xor_sync(0xffffffffu, prow[k], 2), prow[k]);
        }
        if ((lane & 3) == 0) {
            const int g = lane >> 2;
            const int rbase = Ip * 128 + wm * 32;
            float lo, hi;
            upk2(lo, hi, prow[0]); atomicAdd(&g_rowsum[rbase + g],      lo + hi);
            upk2(lo, hi, prow[1]); atomicAdd(&g_rowsum[rbase + g + 8],  lo + hi);
            upk2(lo, hi, prow[2]); atomicAdd(&g_rowsum[rbase + 16 + g], lo + hi);
            upk2(lo, hi, prow[3]); atomicAdd(&g_rowsum[rbase + 24 + g], lo + hi);
        }
        if (Jp != Ip) {
            #pragma unroll
            for (int j = 0; j < 8; j++) {
                pcol[j] = fma2(C1, __shfl_xor_sync(0xffffffffu, pcol[j], 4),  pcol[j]);
                pcol[j] = fma2(C1, __shfl_xor_sync(0xffffffffu, pcol[j], 8),  pcol[j]);
                pcol[j] = fma2(C1, __shfl_xor_sync(0xffffffffu, pcol[j], 16), pcol[j]);
            }
            if (lane < 4) {
                #pragma unroll
                for (int j = 0; j < 8; j++) {
                    float lo, hi;
                    upk2(lo, hi, pcol[j]);
                    const int c = wn * 64 + (j >> 1) * 16 + (j & 1) * 8 + lane * 2;
                    csum2[wm][c]     = lo;
                    csum2[wm][c + 1] = hi;
                }
            }
            __syncthreads();
            if (tid < 128) {
                atomicAdd(&g_rowsum[Jp * 128 + tid],
                          csum2[0][tid] + csum2[1][tid] + csum2[2][tid] + csum2[3][tid]);
            }
        }
        #pragma unroll
        for (int k = 0; k < 4; k++) prow[k] = 0ull;
        #pragma unroll
        for (int k = 0; k < 8; k++) pcol[k] = 0ull;
    };

    for (; t < NTILES; t += GRID_K2) {
        const int tn = t + GRID_K2;
        if (tn < NTILES) {
            decode_tile(tn, In, Jn);
            issue(slot ^ 1, In, Jn);
            CP_ASYNC_WAIT_1();
        } else {
            CP_ASYNC_WAIT_0();
        }
        __syncthreads();   // tile t data visible; also fences csum2 reuse

        const char* base = dynsm + slot * (2 * TILE_BYTES);
        const uint32_t aBase = smem_u32(base) + aLane;
        const uint32_t bBase = smem_u32(base + (J != I ? TILE_BYTES : 0)) + bLane;

        float acc[2][8][4];
        #pragma unroll
        for (int mb = 0; mb < 2; mb++)
            #pragma unroll
            for (int j = 0; j < 8; j++)
                #pragma unroll
                for (int v = 0; v < 4; v++) acc[mb][j][v] = 0.0f;

        // ---- interleaved: MMA(tile t) + poly epilogue chunks(tile t-1) ----
        #pragma unroll
        for (int ks = 0; ks < 8; ks++) {
            uint32_t a0[4], a1[4];
            LDSM_X4(a0, aBase + ks * 32);
            LDSM_X4(a1, aBase + 16 * ROW_BYTES + ks * 32);
            #pragma unroll
            for (int nb = 0; nb < 4; nb++) {
                uint32_t b[4];
                LDSM_X4(b, bBase + nb * 16 * ROW_BYTES + ks * 32);
                MMA_BF16(acc[0][2 * nb],     a0, b[0], b[1]);
                MMA_BF16(acc[0][2 * nb + 1], a0, b[2], b[3]);
                MMA_BF16(acc[1][2 * nb],     a1, b[0], b[1]);
                MMA_BF16(acc[1][2 * nb + 1], a1, b[2], b[3]);
            }
            if (havePrev) epi_chunk(ks);
        }

        if (havePrev) flush_prev();

        // pack tile t accumulators into 'saved' for next iteration's epilogue
        #pragma unroll
        for (int mb = 0; mb < 2; mb++)
            #pragma unroll
            for (int jj = 0; jj < 8; jj++)
                #pragma unroll
                for (int vp = 0; vp < 2; vp++)
                    saved[mb * 16 + jj * 2 + vp] =
                        pk2(acc[mb][jj][2 * vp], acc[mb][jj][2 * vp + 1]);

        havePrev = true;
        Ip = I; Jp = J;
        I = In; J = Jn;
        slot ^= 1;
    }

    // drain: epilogue + flush for the last tile
    #pragma unroll
    for (int c = 0; c < 8; c++) epi_chunk(c);
    flush_prev();
}

// ===================== K3: log + final reduction =====================

__global__ void __launch_bounds__(1024) k3_reduce(float* __restrict__ out) {
    const int t = threadIdx.x;
    float s = 0.0f;
    #pragma unroll
    for (int i = t; i < NTOT; i += 1024) s += logf(g_rowsum[i] - EXP_DIAG);
    #pragma unroll
    for (int r = t; r < BATCH; r += 1024) s -= 2.0f * g_pos[r];
    #pragma unroll
    for (int o = 16; o; o >>= 1) s += __shfl_xor_sync(0xffffffffu, s, o);
    __shared__ float red[32];
    if ((t & 31) == 0) red[t >> 5] = s;
    __syncthreads();
    if (t == 0) {
        float tot = 0.0f;
        #pragma unroll
        for (int w = 0; w < 32; w++) tot += red[w];
        out[0] = tot / (float)NTOT;
    }
}

// ===================== launch =====================

extern "C" void kernel_launch(void* const* d_in, const int* in_sizes, int n_in,
                              void* d_out, int out_size) {
    const float* zi = (const float*)d_in[0];
    const float* zj = (const float*)d_in[1];
    float* out = (float*)d_out;

    cudaFuncSetAttribute(k2_simsum, cudaFuncAttributeMaxDynamicSharedMemorySize, SMEM_BYTES);

    k1_normalize<<<BATCH / 8, 256>>>(zi, zj);
    k2_simsum<<<GRID_K2, 256, SMEM_BYTES>>>();
    k3_reduce<<<1, 1024>>>(out);
}